// round 5
// baseline (speedup 1.0000x reference)
#include <cuda_runtime.h>
#include <cuda_fp16.h>
#include <cstdint>
#include <cstddef>

#define B_   16
#define H_   64
#define W_   64
#define C_   256
#define HP   66
#define WP   66
#define NPOS (B_*H_*W_)     // 65536
#define KDIM 2048
#define NDIM 256

#define BM 64
#define BN 128
#define BK 64               // halves per k-stage (128 B per row)
#define NKT (KDIM / BK)     // 32
#define NSTAGE 3

#define A_BYTES (BM * 128)                 // 8 KB
#define B_BYTES (BN * 128)                 // 16 KB
#define STAGE_BYTES (A_BYTES + B_BYTES)    // 24 KB
#define SM_TOTAL (NSTAGE * STAGE_BYTES)    // 72 KB -> 2 CTAs/SM

__device__ __align__(16) __half g_pad[(size_t)B_ * HP * WP * C_];  // ~35.7 MB
__device__ __align__(16) __half Mt[(size_t)NDIM * KDIM];           // 1 MB

// shift[d] = -dy[d]*WP - dx[d]
__device__ const int c_shift[8] = { 66, 65, -1, -67, -66, -65, 1, 67 };

// ---------------------------------------------------------------------------
__device__ __forceinline__ uint32_t smem_u32(const void* p) {
    uint32_t a;
    asm("{ .reg .u64 t; cvta.to.shared.u64 t, %1; cvt.u32.u64 %0, t; }" : "=r"(a) : "l"(p));
    return a;
}
__device__ __forceinline__ void cp_async16(uint32_t dst, const void* src) {
    asm volatile("cp.async.cg.shared.global [%0], [%1], 16;" :: "r"(dst), "l"(src));
}
__device__ __forceinline__ void cp_commit() {
    asm volatile("cp.async.commit_group;" ::: "memory");
}
template<int N> __device__ __forceinline__ void cp_wait() {
    asm volatile("cp.async.wait_group %0;" :: "n"(N) : "memory");
}
__device__ __forceinline__ void ldsm4(uint32_t& r0, uint32_t& r1, uint32_t& r2, uint32_t& r3,
                                      uint32_t addr) {
    asm volatile("ldmatrix.sync.aligned.m8n8.x4.shared.b16 {%0,%1,%2,%3}, [%4];"
                 : "=r"(r0), "=r"(r1), "=r"(r2), "=r"(r3) : "r"(addr));
}
// f16-accumulate MMA: d0 = {row g, cols 2t,2t+1}, d1 = {row g+8, same cols}
__device__ __forceinline__ void mma16816_f16(uint32_t* d, const uint32_t* a, const uint32_t* b) {
    asm volatile(
        "mma.sync.aligned.m16n8k16.row.col.f16.f16.f16.f16 "
        "{%0,%1}, {%2,%3,%4,%5}, {%6,%7}, {%0,%1};\n"
        : "+r"(d[0]), "+r"(d[1])
        : "r"(a[0]), "r"(a[1]), "r"(a[2]), "r"(a[3]), "r"(b[0]), "r"(b[1]));
}

// ---------------------------------------------------------------------------
// Kernel 1: pad + fp32->fp16 (zero halo), 8 halves per thread
// ---------------------------------------------------------------------------
__global__ __launch_bounds__(256) void pad_convert_kernel(const float* __restrict__ g)
{
    const int gid = blockIdx.x * 256 + threadIdx.x;   // one per 8 channels
    const int pix = gid >> 5;
    const int c8  = (gid & 31) * 8;
    const int xp  = pix % WP;
    const int tmp = pix / WP;
    const int yp  = tmp % HP;
    const int b   = tmp / HP;

    uint4 v = make_uint4(0u, 0u, 0u, 0u);
    if (yp >= 1 && yp <= H_ && xp >= 1 && xp <= W_) {
        const float* src = &g[(((size_t)b * H_ + (yp - 1)) * W_ + (xp - 1)) * C_ + c8];
        const float4 f0 = *(const float4*)(src);
        const float4 f1 = *(const float4*)(src + 4);
        __half2 h0 = __floats2half2_rn(f0.x, f0.y);
        __half2 h1 = __floats2half2_rn(f0.z, f0.w);
        __half2 h2 = __floats2half2_rn(f1.x, f1.y);
        __half2 h3 = __floats2half2_rn(f1.z, f1.w);
        v.x = *(uint32_t*)&h0; v.y = *(uint32_t*)&h1;
        v.z = *(uint32_t*)&h2; v.w = *(uint32_t*)&h3;
    }
    *(uint4*)&g_pad[(size_t)pix * C_ + c8] = v;
}

// ---------------------------------------------------------------------------
// Kernel 2: fold weights  Mt[o][d*256+c] = sum_e Wd[d][c][e] * Wc[o][d*256+e]
// ---------------------------------------------------------------------------
__global__ void fold_weights_kernel(const float* __restrict__ Wd,
                                    const float* __restrict__ Wc)
{
    const int bid = blockIdx.x;
    const int d  = bid >> 4;
    const int ct = (bid >> 2) & 3;
    const int et = bid & 3;

    __shared__ float WdS[64][33];
    __shared__ float WcS[64][33];

    const int t  = threadIdx.x;
    const int tx = t & 15;
    const int ty = t >> 4;

    float acc[4][4];
    #pragma unroll
    for (int i = 0; i < 4; i++)
        #pragma unroll
        for (int j = 0; j < 4; j++) acc[i][j] = 0.0f;

    const float* WdBase = Wd + (size_t)d * C_ * C_ + (size_t)(ct * 64) * C_;
    const float* WcBase = Wc + (size_t)(et * 64) * KDIM + d * C_;

    const int ci  = t >> 2;
    const int kk0 = (t & 3) * 8;

    for (int k0 = 0; k0 < C_; k0 += 32) {
        const float* srcA = WdBase + (size_t)ci * C_   + k0 + kk0;
        const float* srcB = WcBase + (size_t)ci * KDIM + k0 + kk0;
        #pragma unroll
        for (int u = 0; u < 8; u++) WdS[ci][kk0 + u] = srcA[u];
        #pragma unroll
        for (int u = 0; u < 8; u++) WcS[ci][kk0 + u] = srcB[u];
        __syncthreads();
        #pragma unroll
        for (int kk = 0; kk < 32; kk++) {
            float a[4], bb[4];
            #pragma unroll
            for (int i = 0; i < 4; i++) a[i]  = WdS[ty * 4 + i][kk];
            #pragma unroll
            for (int j = 0; j < 4; j++) bb[j] = WcS[tx * 4 + j][kk];
            #pragma unroll
            for (int i = 0; i < 4; i++)
                #pragma unroll
                for (int j = 0; j < 4; j++) acc[i][j] += a[i] * bb[j];
        }
        __syncthreads();
    }
    #pragma unroll
    for (int i = 0; i < 4; i++) {
        const int c = ct * 64 + ty * 4 + i;
        #pragma unroll
        for (int j = 0; j < 4; j++) {
            const int o = et * 64 + tx * 4 + j;
            Mt[(size_t)o * KDIM + d * C_ + c] = __float2half(acc[i][j]);
        }
    }
}

// ---------------------------------------------------------------------------
// Kernel 3: HMMA implicit-GEMM, f16-accumulate with per-BK fp32 promotion.
// BM=64, BN=128, BK=64, 3-stage cp.async. 8 warps (2m x 4n), each 32x32.
// 2048 CTAs, 2 CTAs/SM.
// ---------------------------------------------------------------------------
__global__ __launch_bounds__(256, 2) void conv_gemm_hmma(const float* __restrict__ bias,
                                                         float* __restrict__ out)
{
    extern __shared__ __align__(1024) char smem[];
    const uint32_t sbase = smem_u32(smem);

    const int t    = threadIdx.x;
    const int warp = t >> 5, lane = t & 31;
    const int bx   = blockIdx.x;
    const int m0   = (bx >> 1) * BM;
    const int n0   = (bx & 1) * BN;

    // ---- producer setup ----
    const int arow   = t >> 2;
    const int acpair = (t & 3) * 2;
    const int brow = t >> 1;
    const int bc0  = (t & 1) * 4;

    const int m = m0 + arow;
    const int x = m & 63;
    const int y = (m >> 6) & 63;
    const int b = m >> 12;
    const __half* a_src_base = g_pad + (size_t)((b * HP + y + 1) * WP + (x + 1)) * C_;
    const __half* b_src_base = Mt + (size_t)(n0 + brow) * KDIM;

    uint32_t a_dst[2], b_dst[4];
    #pragma unroll
    for (int j = 0; j < 2; j++)
        a_dst[j] = (uint32_t)(arow * 128 + (((acpair + j) ^ (arow & 7)) << 4));
    #pragma unroll
    for (int j = 0; j < 4; j++)
        b_dst[j] = (uint32_t)(A_BYTES + brow * 128 + (((bc0 + j) ^ (brow & 7)) << 4));

    // ---- consumer setup: warp tile 32x32 ----
    const int wm = (warp >> 2) * 32;
    const int wn = (warp & 3) * 32;
    const int swz  = lane & 7;
    const int a_hi = lane >> 4;
    const int b_hi = (lane >> 3) & 1;

    uint32_t a_row_off[2], b_row_off[2];
    #pragma unroll
    for (int im = 0; im < 2; im++)
        a_row_off[im] = (uint32_t)((wm + im * 16 + (lane & 15)) * 128);
    #pragma unroll
    for (int j2 = 0; j2 < 2; j2++)
        b_row_off[j2] = (uint32_t)(A_BYTES +
            (wn + j2 * 16 + ((lane >> 4) << 3) + (lane & 7)) * 128);

    float acc[2][4][4];
    #pragma unroll
    for (int i = 0; i < 2; i++)
        #pragma unroll
        for (int j = 0; j < 4; j++)
            #pragma unroll
            for (int r = 0; r < 4; r++) acc[i][j][r] = 0.0f;

    #define LOAD_STAGE(KT, S)                                                     \
    do {                                                                          \
        const int d_   = (KT) >> 2;                                               \
        const int coff = ((KT) & 3) * 64 + acpair * 8;                            \
        const __half* asrc = a_src_base + c_shift[d_] * C_ + coff;                \
        const __half* bsrc = b_src_base + (KT) * 64 + bc0 * 8;                    \
        const uint32_t sb  = sbase + (S) * STAGE_BYTES;                           \
        _Pragma("unroll")                                                         \
        for (int j = 0; j < 2; j++) cp_async16(sb + a_dst[j], asrc + j * 8);      \
        _Pragma("unroll")                                                         \
        for (int j = 0; j < 4; j++) cp_async16(sb + b_dst[j], bsrc + j * 8);      \
        cp_commit();                                                              \
    } while (0)

    LOAD_STAGE(0, 0);
    LOAD_STAGE(1, 1);

    for (int s = 0; s < NKT; s++) {
        if (s + 2 < NKT) cp_wait<1>(); else cp_wait<0>();
        __syncthreads();
        if (s + 2 < NKT) LOAD_STAGE(s + 2, (s + 2) % NSTAGE);

        const uint32_t sb = sbase + (s % NSTAGE) * STAGE_BYTES;

        // f16 chunk accumulators (one BK tile = 4 k-steps), zeroed per stage
        uint32_t hacc[2][4][2];
        #pragma unroll
        for (int im = 0; im < 2; im++)
            #pragma unroll
            for (int jn = 0; jn < 4; jn++) {
                hacc[im][jn][0] = 0u; hacc[im][jn][1] = 0u;
            }

        #pragma unroll
        for (int kk = 0; kk < 4; kk++) {
            uint32_t afr[2][4];
            uint32_t bfr[4][2];
            #pragma unroll
            for (int im = 0; im < 2; im++)
                ldsm4(afr[im][0], afr[im][1], afr[im][2], afr[im][3],
                      sb + a_row_off[im] + (((kk * 2 + a_hi) ^ swz) << 4));
            #pragma unroll
            for (int j2 = 0; j2 < 2; j2++) {
                uint32_t r0, r1, r2, r3;
                ldsm4(r0, r1, r2, r3,
                      sb + b_row_off[j2] + (((kk * 2 + b_hi) ^ swz) << 4));
                bfr[j2 * 2 + 0][0] = r0; bfr[j2 * 2 + 0][1] = r1;
                bfr[j2 * 2 + 1][0] = r2; bfr[j2 * 2 + 1][1] = r3;
            }
            #pragma unroll
            for (int im = 0; im < 2; im++)
                #pragma unroll
                for (int jn = 0; jn < 4; jn++)
                    mma16816_f16(hacc[im][jn], afr[im], bfr[jn]);
        }

        // promote f16 chunk sums into fp32 accumulators
        #pragma unroll
        for (int im = 0; im < 2; im++)
            #pragma unroll
            for (int jn = 0; jn < 4; jn++) {
                const float2 lo = __half22float2(*(__half2*)&hacc[im][jn][0]);
                const float2 hi = __half22float2(*(__half2*)&hacc[im][jn][1]);
                acc[im][jn][0] += lo.x;
                acc[im][jn][1] += lo.y;
                acc[im][jn][2] += hi.x;
                acc[im][jn][3] += hi.y;
            }
    }

    // ---- epilogue ----
    #pragma unroll
    for (int jn = 0; jn < 4; jn++) {
        const int n = n0 + wn + jn * 8 + (lane & 3) * 2;
        const float2 bv = *(const float2*)&bias[n];
        #pragma unroll
        for (int im = 0; im < 2; im++) {
            const int mrow = m0 + wm + im * 16 + (lane >> 2);
            float2 v0, v1;
            v0.x = acc[im][jn][0] + bv.x;  v0.y = acc[im][jn][1] + bv.y;
            v1.x = acc[im][jn][2] + bv.x;  v1.y = acc[im][jn][3] + bv.y;
            *(float2*)&out[(size_t)mrow * NDIM + n]       = v0;
            *(float2*)&out[(size_t)(mrow + 8) * NDIM + n] = v1;
        }
    }
}

// ---------------------------------------------------------------------------
extern "C" void kernel_launch(void* const* d_in, const int* in_sizes, int n_in,
                              void* d_out, int out_size)
{
    const float* grid = (const float*)d_in[0];
    const float* Wd   = (const float*)d_in[1];
    const float* Wc   = (const float*)d_in[2];
    const float* bc   = (const float*)d_in[3];
    float* out        = (float*)d_out;

    cudaFuncSetAttribute(conv_gemm_hmma, cudaFuncAttributeMaxDynamicSharedMemorySize, SM_TOTAL);

    pad_convert_kernel<<<(B_ * HP * WP * 32) / 256, 256>>>(grid);
    fold_weights_kernel<<<128, 256>>>(Wd, Wc);
    conv_gemm_hmma<<<(NPOS / BM) * (NDIM / BN), 256, SM_TOTAL>>>(bc, out);
}

// round 6
// speedup vs baseline: 1.1523x; 1.1523x over previous
#include <cuda_runtime.h>
#include <cuda_fp16.h>
#include <cstdint>
#include <cstddef>

#define B_   16
#define H_   64
#define W_   64
#define C_   256
#define HP   66
#define WP   66
#define NDIM 256
#define NTILES 16384                 // 16 * 32 * 32 (2x2 output tiles)
#define TILEC  ((size_t)NTILES * 256)

// GEMM tiling (K = 256 per Winograd point)
#define KD2  256
#define BM 64
#define BN 128
#define BK 64
#define NKT (KD2 / BK)               // 4
#define NSTAGE 3
#define A_BYTES (BM * 128)
#define B_BYTES (BN * 128)
#define STAGE_BYTES (A_BYTES + B_BYTES)   // 24 KB
#define SM_TOTAL (NSTAGE * STAGE_BYTES)   // 72 KB

__device__ __align__(16) __half g_pad[(size_t)B_ * HP * WP * C_];  // 35.7 MB
__device__ __align__(16) float  Mf[(size_t)C_ * 256 * 8];          // [c][o][d] 2 MB
__device__ __align__(16) __half U_buf[(size_t)16 * 256 * 256];     // [k][o][c] 2 MB
__device__ __align__(16) __half V_buf[(size_t)16 * TILEC];         // [k][tile][c] 128 MB
__device__ __align__(16) float  Mw[(size_t)16 * TILEC];            // [k][tile][o] 256 MB

// ---------------------------------------------------------------------------
__device__ __forceinline__ uint32_t smem_u32(const void* p) {
    uint32_t a;
    asm("{ .reg .u64 t; cvta.to.shared.u64 t, %1; cvt.u32.u64 %0, t; }" : "=r"(a) : "l"(p));
    return a;
}
__device__ __forceinline__ void cp_async16(uint32_t dst, const void* src) {
    asm volatile("cp.async.cg.shared.global [%0], [%1], 16;" :: "r"(dst), "l"(src));
}
__device__ __forceinline__ void cp_commit() {
    asm volatile("cp.async.commit_group;" ::: "memory");
}
template<int N> __device__ __forceinline__ void cp_wait() {
    asm volatile("cp.async.wait_group %0;" :: "n"(N) : "memory");
}
__device__ __forceinline__ void ldsm4(uint32_t& r0, uint32_t& r1, uint32_t& r2, uint32_t& r3,
                                      uint32_t addr) {
    asm volatile("ldmatrix.sync.aligned.m8n8.x4.shared.b16 {%0,%1,%2,%3}, [%4];"
                 : "=r"(r0), "=r"(r1), "=r"(r2), "=r"(r3) : "r"(addr));
}
__device__ __forceinline__ void mma16816(float* d, const uint32_t* a, const uint32_t* b) {
    asm volatile(
        "mma.sync.aligned.m16n8k16.row.col.f32.f16.f16.f32 "
        "{%0,%1,%2,%3}, {%4,%5,%6,%7}, {%8,%9}, {%0,%1,%2,%3};\n"
        : "+f"(d[0]), "+f"(d[1]), "+f"(d[2]), "+f"(d[3])
        : "r"(a[0]), "r"(a[1]), "r"(a[2]), "r"(a[3]), "r"(b[0]), "r"(b[1]));
}
__device__ __forceinline__ float2 f2add(float2 a, float2 b) { return make_float2(a.x + b.x, a.y + b.y); }
__device__ __forceinline__ float2 f2sub(float2 a, float2 b) { return make_float2(a.x - b.x, a.y - b.y); }

// ---------------------------------------------------------------------------
// Kernel 1: pad + fp32->fp16 (zero halo)
// ---------------------------------------------------------------------------
__global__ __launch_bounds__(256) void pad_convert_kernel(const float* __restrict__ g)
{
    const int gid = blockIdx.x * 256 + threadIdx.x;
    const int pix = gid >> 5;
    const int c8  = (gid & 31) * 8;
    const int xp  = pix % WP;
    const int tmp = pix / WP;
    const int yp  = tmp % HP;
    const int b   = tmp / HP;

    uint4 v = make_uint4(0u, 0u, 0u, 0u);
    if (yp >= 1 && yp <= H_ && xp >= 1 && xp <= W_) {
        const float* src = &g[(((size_t)b * H_ + (yp - 1)) * W_ + (xp - 1)) * C_ + c8];
        const float4 f0 = *(const float4*)(src);
        const float4 f1 = *(const float4*)(src + 4);
        __half2 h0 = __floats2half2_rn(f0.x, f0.y);
        __half2 h1 = __floats2half2_rn(f0.z, f0.w);
        __half2 h2 = __floats2half2_rn(f1.x, f1.y);
        __half2 h3 = __floats2half2_rn(f1.z, f1.w);
        v.x = *(uint32_t*)&h0; v.y = *(uint32_t*)&h1;
        v.z = *(uint32_t*)&h2; v.w = *(uint32_t*)&h3;
    }
    *(uint4*)&g_pad[(size_t)pix * C_ + c8] = v;
}

// ---------------------------------------------------------------------------
// Kernel 2: fold weights -> Mf[c][o][d] (fp32)
//   Mf = sum_e Wd[d][c][e] * Wc[o][d*256+e]
// ---------------------------------------------------------------------------
__global__ void fold_weights_kernel(const float* __restrict__ Wd,
                                    const float* __restrict__ Wc)
{
    const int bid = blockIdx.x;
    const int d  = bid >> 4;
    const int ct = (bid >> 2) & 3;
    const int et = bid & 3;

    __shared__ float WdS[64][33];
    __shared__ float WcS[64][33];

    const int t  = threadIdx.x;
    const int tx = t & 15;
    const int ty = t >> 4;

    float acc[4][4];
    #pragma unroll
    for (int i = 0; i < 4; i++)
        #pragma unroll
        for (int j = 0; j < 4; j++) acc[i][j] = 0.0f;

    const float* WdBase = Wd + (size_t)d * C_ * C_ + (size_t)(ct * 64) * C_;
    const float* WcBase = Wc + (size_t)(et * 64) * (8 * C_) + d * C_;

    const int ci  = t >> 2;
    const int kk0 = (t & 3) * 8;

    for (int k0 = 0; k0 < C_; k0 += 32) {
        const float* srcA = WdBase + (size_t)ci * C_        + k0 + kk0;
        const float* srcB = WcBase + (size_t)ci * (8 * C_)  + k0 + kk0;
        #pragma unroll
        for (int u = 0; u < 8; u++) WdS[ci][kk0 + u] = srcA[u];
        #pragma unroll
        for (int u = 0; u < 8; u++) WcS[ci][kk0 + u] = srcB[u];
        __syncthreads();
        #pragma unroll
        for (int kk = 0; kk < 32; kk++) {
            float a[4], bb[4];
            #pragma unroll
            for (int i = 0; i < 4; i++) a[i]  = WdS[ty * 4 + i][kk];
            #pragma unroll
            for (int j = 0; j < 4; j++) bb[j] = WcS[tx * 4 + j][kk];
            #pragma unroll
            for (int i = 0; i < 4; i++)
                #pragma unroll
                for (int j = 0; j < 4; j++) acc[i][j] += a[i] * bb[j];
        }
        __syncthreads();
    }
    #pragma unroll
    for (int i = 0; i < 4; i++) {
        const int c = ct * 64 + ty * 4 + i;
        #pragma unroll
        for (int j = 0; j < 4; j++) {
            const int o = et * 64 + tx * 4 + j;
            Mf[((size_t)c * 256 + o) * 8 + d] = acc[i][j];
        }
    }
}

// ---------------------------------------------------------------------------
// Kernel 3: weight transform U_k = G K G^T  (k = a*4+b), fp16 [k][o][c]
// K[1-dy][1-dx] = M_d (center zero):
//   K00=m3 K01=m4 K02=m5 / K10=m2 K11=0 K12=m6 / K20=m1 K21=m0 K22=m7
// ---------------------------------------------------------------------------
__global__ __launch_bounds__(256) void weight_transform_kernel()
{
    const int o = blockIdx.x;
    const int c = threadIdx.x;

    const float* mp = &Mf[((size_t)c * 256 + o) * 8];
    float m[8];
    const float4 f0 = *(const float4*)(mp);
    const float4 f1 = *(const float4*)(mp + 4);
    m[0]=f0.x; m[1]=f0.y; m[2]=f0.z; m[3]=f0.w;
    m[4]=f1.x; m[5]=f1.y; m[6]=f1.z; m[7]=f1.w;

    float K[3][3];
    K[0][0]=m[3]; K[0][1]=m[4]; K[0][2]=m[5];
    K[1][0]=m[2]; K[1][1]=0.f;  K[1][2]=m[6];
    K[2][0]=m[1]; K[2][1]=m[0]; K[2][2]=m[7];

    float T[4][3];
    #pragma unroll
    for (int j = 0; j < 3; j++) {
        T[0][j] = K[0][j];
        T[1][j] = 0.5f * (K[0][j] + K[1][j] + K[2][j]);
        T[2][j] = 0.5f * (K[0][j] - K[1][j] + K[2][j]);
        T[3][j] = K[2][j];
    }
    #pragma unroll
    for (int a = 0; a < 4; a++) {
        float U0 = T[a][0];
        float U1 = 0.5f * (T[a][0] + T[a][1] + T[a][2]);
        float U2 = 0.5f * (T[a][0] - T[a][1] + T[a][2]);
        float U3 = T[a][2];
        U_buf[(size_t)(a * 4 + 0) * 65536 + o * 256 + c] = __float2half(U0);
        U_buf[(size_t)(a * 4 + 1) * 65536 + o * 256 + c] = __float2half(U1);
        U_buf[(size_t)(a * 4 + 2) * 65536 + o * 256 + c] = __float2half(U2);
        U_buf[(size_t)(a * 4 + 3) * 65536 + o * 256 + c] = __float2half(U3);
    }
}

// ---------------------------------------------------------------------------
// Kernel 4: input transform V = B^T d B per (tile, channel-pair)
// tile (b,ty,tx): d = g_pad[b][2ty : 2ty+4][2tx : 2tx+4][c]
// ---------------------------------------------------------------------------
__global__ __launch_bounds__(256) void input_transform_kernel()
{
    const int tid  = threadIdx.x;
    const int tile = blockIdx.x * 2 + (tid >> 7);
    const int c    = (tid & 127) * 2;

    const int b  = tile >> 10;
    const int ty = (tile >> 5) & 31;
    const int tx = tile & 31;

    const __half* base = &g_pad[(((size_t)b * HP + 2 * ty) * WP + 2 * tx) * C_ + c];

    float2 d[4][4];
    #pragma unroll
    for (int i = 0; i < 4; i++)
        #pragma unroll
        for (int j = 0; j < 4; j++)
            d[i][j] = __half22float2(*(const __half2*)(base + ((size_t)i * WP + j) * C_));

    float2 tr[4][4];
    #pragma unroll
    for (int j = 0; j < 4; j++) {
        tr[0][j] = f2sub(d[0][j], d[2][j]);
        tr[1][j] = f2add(d[1][j], d[2][j]);
        tr[2][j] = f2sub(d[2][j], d[1][j]);
        tr[3][j] = f2sub(d[1][j], d[3][j]);
    }
    #pragma unroll
    for (int a = 0; a < 4; a++) {
        float2 V0 = f2sub(tr[a][0], tr[a][2]);
        float2 V1 = f2add(tr[a][1], tr[a][2]);
        float2 V2 = f2sub(tr[a][2], tr[a][1]);
        float2 V3 = f2sub(tr[a][1], tr[a][3]);
        *(__half2*)&V_buf[(size_t)(a * 4 + 0) * TILEC + (size_t)tile * 256 + c] = __float22half2_rn(V0);
        *(__half2*)&V_buf[(size_t)(a * 4 + 1) * TILEC + (size_t)tile * 256 + c] = __float22half2_rn(V1);
        *(__half2*)&V_buf[(size_t)(a * 4 + 2) * TILEC + (size_t)tile * 256 + c] = __float22half2_rn(V2);
        *(__half2*)&V_buf[(size_t)(a * 4 + 3) * TILEC + (size_t)tile * 256 + c] = __float22half2_rn(V3);
    }
}

// ---------------------------------------------------------------------------
// Kernel 5: 16 x GEMM [16384, 256, 256]: Mw_k = V_k @ U_k^T  (f32 acc)
// blockIdx.y = k. BM=64, BN=128, BK=64, 3-stage cp.async, ldmatrix.
// ---------------------------------------------------------------------------
__global__ __launch_bounds__(256, 2) void wino_gemm(void)
{
    extern __shared__ __align__(1024) char smem[];
    const uint32_t sbase = smem_u32(smem);

    const int t    = threadIdx.x;
    const int warp = t >> 5, lane = t & 31;
    const int bx   = blockIdx.x;
    const int k    = blockIdx.y;
    const int m0   = (bx >> 1) * BM;
    const int n0   = (bx & 1) * BN;

    // ---- producer setup ----
    const int arow   = t >> 2;
    const int acpair = (t & 3) * 2;
    const int brow = t >> 1;
    const int bc0  = (t & 1) * 4;

    const __half* a_src_base = V_buf + (size_t)k * TILEC + (size_t)(m0 + arow) * KD2;
    const __half* b_src_base = U_buf + (size_t)k * 65536 + (size_t)(n0 + brow) * KD2;

    uint32_t a_dst[2], b_dst[4];
    #pragma unroll
    for (int j = 0; j < 2; j++)
        a_dst[j] = (uint32_t)(arow * 128 + (((acpair + j) ^ (arow & 7)) << 4));
    #pragma unroll
    for (int j = 0; j < 4; j++)
        b_dst[j] = (uint32_t)(A_BYTES + brow * 128 + (((bc0 + j) ^ (brow & 7)) << 4));

    // ---- consumer setup: warp tile 32x32 ----
    const int wm = (warp >> 2) * 32;
    const int wn = (warp & 3) * 32;
    const int swz  = lane & 7;
    const int a_hi = lane >> 4;
    const int b_hi = (lane >> 3) & 1;

    uint32_t a_row_off[2], b_row_off[2];
    #pragma unroll
    for (int im = 0; im < 2; im++)
        a_row_off[im] = (uint32_t)((wm + im * 16 + (lane & 15)) * 128);
    #pragma unroll
    for (int j2 = 0; j2 < 2; j2++)
        b_row_off[j2] = (uint32_t)(A_BYTES +
            (wn + j2 * 16 + ((lane >> 4) << 3) + (lane & 7)) * 128);

    float acc[2][4][4];
    #pragma unroll
    for (int i = 0; i < 2; i++)
        #pragma unroll
        for (int j = 0; j < 4; j++)
            #pragma unroll
            for (int r = 0; r < 4; r++) acc[i][j][r] = 0.0f;

    #define LOAD_STAGE(KT, S)                                                     \
    do {                                                                          \
        const __half* asrc = a_src_base + (KT) * 64 + acpair * 8;                 \
        const __half* bsrc = b_src_base + (KT) * 64 + bc0 * 8;                    \
        const uint32_t sb  = sbase + (S) * STAGE_BYTES;                           \
        _Pragma("unroll")                                                         \
        for (int j = 0; j < 2; j++) cp_async16(sb + a_dst[j], asrc + j * 8);      \
        _Pragma("unroll")                                                         \
        for (int j = 0; j < 4; j++) cp_async16(sb + b_dst[j], bsrc + j * 8);      \
        cp_commit();                                                              \
    } while (0)

    LOAD_STAGE(0, 0);
    LOAD_STAGE(1, 1);

    for (int s = 0; s < NKT; s++) {
        if (s + 2 < NKT) cp_wait<1>(); else cp_wait<0>();
        __syncthreads();
        if (s + 2 < NKT) LOAD_STAGE(s + 2, (s + 2) % NSTAGE);

        const uint32_t sb = sbase + (s % NSTAGE) * STAGE_BYTES;
        #pragma unroll
        for (int kk = 0; kk < 4; kk++) {
            uint32_t afr[2][4];
            uint32_t bfr[4][2];
            #pragma unroll
            for (int im = 0; im < 2; im++)
                ldsm4(afr[im][0], afr[im][1], afr[im][2], afr[im][3],
                      sb + a_row_off[im] + (((kk * 2 + a_hi) ^ swz) << 4));
            #pragma unroll
            for (int j2 = 0; j2 < 2; j2++) {
                uint32_t r0, r1, r2, r3;
                ldsm4(r0, r1, r2, r3,
                      sb + b_row_off[j2] + (((kk * 2 + b_hi) ^ swz) << 4));
                bfr[j2 * 2 + 0][0] = r0; bfr[j2 * 2 + 0][1] = r1;
                bfr[j2 * 2 + 1][0] = r2; bfr[j2 * 2 + 1][1] = r3;
            }
            #pragma unroll
            for (int im = 0; im < 2; im++)
                #pragma unroll
                for (int jn = 0; jn < 4; jn++)
                    mma16816(acc[im][jn], afr[im], bfr[jn]);
        }
    }

    // ---- epilogue: write Mw fp32, no bias ----
    float* mw = Mw + (size_t)k * TILEC;
    #pragma unroll
    for (int jn = 0; jn < 4; jn++) {
        const int n = n0 + wn + jn * 8 + (lane & 3) * 2;
        #pragma unroll
        for (int im = 0; im < 2; im++) {
            const int mrow = m0 + wm + im * 16 + (lane >> 2);
            float2 v0, v1;
            v0.x = acc[im][jn][0]; v0.y = acc[im][jn][1];
            v1.x = acc[im][jn][2]; v1.y = acc[im][jn][3];
            *(float2*)&mw[(size_t)mrow * NDIM + n]       = v0;
            *(float2*)&mw[(size_t)(mrow + 8) * NDIM + n] = v1;
        }
    }
}

// ---------------------------------------------------------------------------
// Kernel 6: output transform Y = A^T M A + bias, scatter to out
// ---------------------------------------------------------------------------
__global__ __launch_bounds__(256) void output_transform_kernel(const float* __restrict__ bias,
                                                               float* __restrict__ out)
{
    const int tid  = threadIdx.x;
    const int tile = blockIdx.x * 2 + (tid >> 7);
    const int o    = (tid & 127) * 2;

    const int b  = tile >> 10;
    const int ty = (tile >> 5) & 31;
    const int tx = tile & 31;

    float2 M[4][4];
    #pragma unroll
    for (int a = 0; a < 4; a++)
        #pragma unroll
        for (int bb = 0; bb < 4; bb++)
            M[a][bb] = *(const float2*)&Mw[(size_t)(a * 4 + bb) * TILEC + (size_t)tile * 256 + o];

    float2 s0[4], s1[4];
    #pragma unroll
    for (int bb = 0; bb < 4; bb++) {
        s0[bb] = f2add(f2add(M[0][bb], M[1][bb]), M[2][bb]);
        s1[bb] = f2sub(f2sub(M[1][bb], M[2][bb]), M[3][bb]);
    }
    const float2 bv = *(const float2*)&bias[o];
    float2 Y00 = f2add(f2add(f2add(s0[0], s0[1]), s0[2]), bv);
    float2 Y01 = f2add(f2sub(f2sub(s0[1], s0[2]), s0[3]), bv);
    float2 Y10 = f2add(f2add(f2add(s1[0], s1[1]), s1[2]), bv);
    float2 Y11 = f2add(f2sub(f2sub(s1[1], s1[2]), s1[3]), bv);

    const int y0 = 2 * ty, x0 = 2 * tx;
    float* obase = out + ((size_t)b * H_ * W_) * NDIM + o;
    *(float2*)&obase[((size_t)y0 * W_ + x0) * NDIM]           = Y00;
    *(float2*)&obase[((size_t)y0 * W_ + x0 + 1) * NDIM]       = Y01;
    *(float2*)&obase[((size_t)(y0 + 1) * W_ + x0) * NDIM]     = Y10;
    *(float2*)&obase[((size_t)(y0 + 1) * W_ + x0 + 1) * NDIM] = Y11;
}

// ---------------------------------------------------------------------------
extern "C" void kernel_launch(void* const* d_in, const int* in_sizes, int n_in,
                              void* d_out, int out_size)
{
    const float* grid = (const float*)d_in[0];
    const float* Wd   = (const float*)d_in[1];
    const float* Wc   = (const float*)d_in[2];
    const float* bc   = (const float*)d_in[3];
    float* out        = (float*)d_out;

    cudaFuncSetAttribute(wino_gemm, cudaFuncAttributeMaxDynamicSharedMemorySize, SM_TOTAL);

    pad_convert_kernel<<<(B_ * HP * WP * 32) / 256, 256>>>(grid);
    fold_weights_kernel<<<128, 256>>>(Wd, Wc);
    weight_transform_kernel<<<256, 256>>>();
    input_transform_kernel<<<NTILES / 2, 256>>>();
    wino_gemm<<<dim3((NTILES / BM) * 2, 16), 256, SM_TOTAL>>>();
    output_transform_kernel<<<NTILES / 2, 256>>>(bc, out);
}

// round 7
// speedup vs baseline: 1.3476x; 1.1695x over previous
#include <cuda_runtime.h>
#include <cuda_fp16.h>
#include <cstdint>
#include <cstddef>

#define B_   16
#define H_   64
#define W_   64
#define C_   256
#define NDIM 256
#define NTILES 16384                 // 16 * 32 * 32 (2x2 output tiles)
#define TILEC  ((size_t)NTILES * 256)

// GEMM tiling (K = 256 per Winograd point)
#define KD2  256
#define BM 64
#define BN 128
#define BK 64
#define NKT (KD2 / BK)               // 4
#define NSTAGE 3
#define A_BYTES (BM * 128)
#define B_BYTES (BN * 128)
#define STAGE_BYTES (A_BYTES + B_BYTES)   // 24 KB
#define SM_TOTAL (NSTAGE * STAGE_BYTES)   // 72 KB

__device__ __align__(16) float  Mf[(size_t)C_ * 256 * 8];          // [c][o][d] 2 MB
__device__ __align__(16) __half U_buf[(size_t)16 * 256 * 256];     // [k][o][c] 2 MB
__device__ __align__(16) __half V_buf[(size_t)16 * TILEC];         // [k][tile][c] 128 MB
__device__ __align__(16) __half Mw_h[(size_t)16 * TILEC];          // [k][tile][o] 128 MB

// ---------------------------------------------------------------------------
__device__ __forceinline__ uint32_t smem_u32(const void* p) {
    uint32_t a;
    asm("{ .reg .u64 t; cvta.to.shared.u64 t, %1; cvt.u32.u64 %0, t; }" : "=r"(a) : "l"(p));
    return a;
}
__device__ __forceinline__ void cp_async16(uint32_t dst, const void* src) {
    asm volatile("cp.async.cg.shared.global [%0], [%1], 16;" :: "r"(dst), "l"(src));
}
__device__ __forceinline__ void cp_commit() {
    asm volatile("cp.async.commit_group;" ::: "memory");
}
template<int N> __device__ __forceinline__ void cp_wait() {
    asm volatile("cp.async.wait_group %0;" :: "n"(N) : "memory");
}
__device__ __forceinline__ void ldsm4(uint32_t& r0, uint32_t& r1, uint32_t& r2, uint32_t& r3,
                                      uint32_t addr) {
    asm volatile("ldmatrix.sync.aligned.m8n8.x4.shared.b16 {%0,%1,%2,%3}, [%4];"
                 : "=r"(r0), "=r"(r1), "=r"(r2), "=r"(r3) : "r"(addr));
}
__device__ __forceinline__ void mma16816(float* d, const uint32_t* a, const uint32_t* b) {
    asm volatile(
        "mma.sync.aligned.m16n8k16.row.col.f32.f16.f16.f32 "
        "{%0,%1,%2,%3}, {%4,%5,%6,%7}, {%8,%9}, {%0,%1,%2,%3};\n"
        : "+f"(d[0]), "+f"(d[1]), "+f"(d[2]), "+f"(d[3])
        : "r"(a[0]), "r"(a[1]), "r"(a[2]), "r"(a[3]), "r"(b[0]), "r"(b[1]));
}
__device__ __forceinline__ float2 f2add(float2 a, float2 b) { return make_float2(a.x + b.x, a.y + b.y); }
__device__ __forceinline__ float2 f2sub(float2 a, float2 b) { return make_float2(a.x - b.x, a.y - b.y); }

// ---------------------------------------------------------------------------
// Kernel 1: fold weights -> Mf[c][o][d] (fp32)
//   Mf = sum_e Wd[d][c][e] * Wc[o][d*256+e]
// ---------------------------------------------------------------------------
__global__ void fold_weights_kernel(const float* __restrict__ Wd,
                                    const float* __restrict__ Wc)
{
    const int bid = blockIdx.x;
    const int d  = bid >> 4;
    const int ct = (bid >> 2) & 3;
    const int et = bid & 3;

    __shared__ float WdS[64][33];
    __shared__ float WcS[64][33];

    const int t  = threadIdx.x;
    const int tx = t & 15;
    const int ty = t >> 4;

    float acc[4][4];
    #pragma unroll
    for (int i = 0; i < 4; i++)
        #pragma unroll
        for (int j = 0; j < 4; j++) acc[i][j] = 0.0f;

    const float* WdBase = Wd + (size_t)d * C_ * C_ + (size_t)(ct * 64) * C_;
    const float* WcBase = Wc + (size_t)(et * 64) * (8 * C_) + d * C_;

    const int ci  = t >> 2;
    const int kk0 = (t & 3) * 8;

    for (int k0 = 0; k0 < C_; k0 += 32) {
        const float* srcA = WdBase + (size_t)ci * C_        + k0 + kk0;
        const float* srcB = WcBase + (size_t)ci * (8 * C_)  + k0 + kk0;
        #pragma unroll
        for (int u = 0; u < 8; u++) WdS[ci][kk0 + u] = srcA[u];
        #pragma unroll
        for (int u = 0; u < 8; u++) WcS[ci][kk0 + u] = srcB[u];
        __syncthreads();
        #pragma unroll
        for (int kk = 0; kk < 32; kk++) {
            float a[4], bb[4];
            #pragma unroll
            for (int i = 0; i < 4; i++) a[i]  = WdS[ty * 4 + i][kk];
            #pragma unroll
            for (int j = 0; j < 4; j++) bb[j] = WcS[tx * 4 + j][kk];
            #pragma unroll
            for (int i = 0; i < 4; i++)
                #pragma unroll
                for (int j = 0; j < 4; j++) acc[i][j] += a[i] * bb[j];
        }
        __syncthreads();
    }
    #pragma unroll
    for (int i = 0; i < 4; i++) {
        const int c = ct * 64 + ty * 4 + i;
        #pragma unroll
        for (int j = 0; j < 4; j++) {
            const int o = et * 64 + tx * 4 + j;
            Mf[((size_t)c * 256 + o) * 8 + d] = acc[i][j];
        }
    }
}

// ---------------------------------------------------------------------------
// Kernel 2: weight transform U_k = G K G^T  (k = a*4+b), fp16 [k][o][c]
// K[1-dy][1-dx] = M_d (center zero):
//   K00=m3 K01=m4 K02=m5 / K10=m2 K11=0 K12=m6 / K20=m1 K21=m0 K22=m7
// ---------------------------------------------------------------------------
__global__ __launch_bounds__(256) void weight_transform_kernel()
{
    const int o = blockIdx.x;
    const int c = threadIdx.x;

    const float* mp = &Mf[((size_t)c * 256 + o) * 8];
    float m[8];
    const float4 f0 = *(const float4*)(mp);
    const float4 f1 = *(const float4*)(mp + 4);
    m[0]=f0.x; m[1]=f0.y; m[2]=f0.z; m[3]=f0.w;
    m[4]=f1.x; m[5]=f1.y; m[6]=f1.z; m[7]=f1.w;

    float K[3][3];
    K[0][0]=m[3]; K[0][1]=m[4]; K[0][2]=m[5];
    K[1][0]=m[2]; K[1][1]=0.f;  K[1][2]=m[6];
    K[2][0]=m[1]; K[2][1]=m[0]; K[2][2]=m[7];

    float T[4][3];
    #pragma unroll
    for (int j = 0; j < 3; j++) {
        T[0][j] = K[0][j];
        T[1][j] = 0.5f * (K[0][j] + K[1][j] + K[2][j]);
        T[2][j] = 0.5f * (K[0][j] - K[1][j] + K[2][j]);
        T[3][j] = K[2][j];
    }
    #pragma unroll
    for (int a = 0; a < 4; a++) {
        float U0 = T[a][0];
        float U1 = 0.5f * (T[a][0] + T[a][1] + T[a][2]);
        float U2 = 0.5f * (T[a][0] - T[a][1] + T[a][2]);
        float U3 = T[a][2];
        U_buf[(size_t)(a * 4 + 0) * 65536 + o * 256 + c] = __float2half(U0);
        U_buf[(size_t)(a * 4 + 1) * 65536 + o * 256 + c] = __float2half(U1);
        U_buf[(size_t)(a * 4 + 2) * 65536 + o * 256 + c] = __float2half(U2);
        U_buf[(size_t)(a * 4 + 3) * 65536 + o * 256 + c] = __float2half(U3);
    }
}

// ---------------------------------------------------------------------------
// Kernel 3: FUSED pad + input transform. Reads fp32 grid directly (zero-pad
// via masks), computes V = B^T d B in fp32, stores fp16.
// tile (b,ty,tx): d = grid_zeropad[b][2ty-1 : 2ty+3][2tx-1 : 2tx+3][c]
// ---------------------------------------------------------------------------
__global__ __launch_bounds__(256) void input_transform_kernel(const float* __restrict__ g)
{
    const int tid  = threadIdx.x;
    const int tile = blockIdx.x * 2 + (tid >> 7);
    const int c    = (tid & 127) * 2;

    const int b  = tile >> 10;
    const int ty = (tile >> 5) & 31;
    const int tx = tile & 31;

    const int gy0 = 2 * ty - 1;
    const int gx0 = 2 * tx - 1;
    const float* gbase = g + ((size_t)b * H_ * W_) * C_ + c;

    float2 d[4][4];
    #pragma unroll
    for (int i = 0; i < 4; i++) {
        const int gy = gy0 + i;
        const bool vy = (gy >= 0) && (gy < H_);
        #pragma unroll
        for (int j = 0; j < 4; j++) {
            const int gx = gx0 + j;
            if (vy && gx >= 0 && gx < W_)
                d[i][j] = *(const float2*)(gbase + ((size_t)gy * W_ + gx) * C_);
            else
                d[i][j] = make_float2(0.0f, 0.0f);
        }
    }

    float2 tr[4][4];
    #pragma unroll
    for (int j = 0; j < 4; j++) {
        tr[0][j] = f2sub(d[0][j], d[2][j]);
        tr[1][j] = f2add(d[1][j], d[2][j]);
        tr[2][j] = f2sub(d[2][j], d[1][j]);
        tr[3][j] = f2sub(d[1][j], d[3][j]);
    }
    #pragma unroll
    for (int a = 0; a < 4; a++) {
        float2 V0 = f2sub(tr[a][0], tr[a][2]);
        float2 V1 = f2add(tr[a][1], tr[a][2]);
        float2 V2 = f2sub(tr[a][2], tr[a][1]);
        float2 V3 = f2sub(tr[a][1], tr[a][3]);
        *(__half2*)&V_buf[(size_t)(a * 4 + 0) * TILEC + (size_t)tile * 256 + c] = __float22half2_rn(V0);
        *(__half2*)&V_buf[(size_t)(a * 4 + 1) * TILEC + (size_t)tile * 256 + c] = __float22half2_rn(V1);
        *(__half2*)&V_buf[(size_t)(a * 4 + 2) * TILEC + (size_t)tile * 256 + c] = __float22half2_rn(V2);
        *(__half2*)&V_buf[(size_t)(a * 4 + 3) * TILEC + (size_t)tile * 256 + c] = __float22half2_rn(V3);
    }
}

// ---------------------------------------------------------------------------
// Kernel 4: 16 x GEMM [16384, 256, 256]: Mw_k = V_k @ U_k^T  (f32 acc, fp16 out)
// blockIdx.y = k. BM=64, BN=128, BK=64, 3-stage cp.async, ldmatrix.
// ---------------------------------------------------------------------------
__global__ __launch_bounds__(256, 2) void wino_gemm(void)
{
    extern __shared__ __align__(1024) char smem[];
    const uint32_t sbase = smem_u32(smem);

    const int t    = threadIdx.x;
    const int warp = t >> 5, lane = t & 31;
    const int bx   = blockIdx.x;
    const int k    = blockIdx.y;
    const int m0   = (bx >> 1) * BM;
    const int n0   = (bx & 1) * BN;

    // ---- producer setup ----
    const int arow   = t >> 2;
    const int acpair = (t & 3) * 2;
    const int brow = t >> 1;
    const int bc0  = (t & 1) * 4;

    const __half* a_src_base = V_buf + (size_t)k * TILEC + (size_t)(m0 + arow) * KD2;
    const __half* b_src_base = U_buf + (size_t)k * 65536 + (size_t)(n0 + brow) * KD2;

    uint32_t a_dst[2], b_dst[4];
    #pragma unroll
    for (int j = 0; j < 2; j++)
        a_dst[j] = (uint32_t)(arow * 128 + (((acpair + j) ^ (arow & 7)) << 4));
    #pragma unroll
    for (int j = 0; j < 4; j++)
        b_dst[j] = (uint32_t)(A_BYTES + brow * 128 + (((bc0 + j) ^ (brow & 7)) << 4));

    // ---- consumer setup: warp tile 32x32 ----
    const int wm = (warp >> 2) * 32;
    const int wn = (warp & 3) * 32;
    const int swz  = lane & 7;
    const int a_hi = lane >> 4;
    const int b_hi = (lane >> 3) & 1;

    uint32_t a_row_off[2], b_row_off[2];
    #pragma unroll
    for (int im = 0; im < 2; im++)
        a_row_off[im] = (uint32_t)((wm + im * 16 + (lane & 15)) * 128);
    #pragma unroll
    for (int j2 = 0; j2 < 2; j2++)
        b_row_off[j2] = (uint32_t)(A_BYTES +
            (wn + j2 * 16 + ((lane >> 4) << 3) + (lane & 7)) * 128);

    float acc[2][4][4];
    #pragma unroll
    for (int i = 0; i < 2; i++)
        #pragma unroll
        for (int j = 0; j < 4; j++)
            #pragma unroll
            for (int r = 0; r < 4; r++) acc[i][j][r] = 0.0f;

    #define LOAD_STAGE(KT, S)                                                     \
    do {                                                                          \
        const __half* asrc = a_src_base + (KT) * 64 + acpair * 8;                 \
        const __half* bsrc = b_src_base + (KT) * 64 + bc0 * 8;                    \
        const uint32_t sb  = sbase + (S) * STAGE_BYTES;                           \
        _Pragma("unroll")                                                         \
        for (int j = 0; j < 2; j++) cp_async16(sb + a_dst[j], asrc + j * 8);      \
        _Pragma("unroll")                                                         \
        for (int j = 0; j < 4; j++) cp_async16(sb + b_dst[j], bsrc + j * 8);      \
        cp_commit();                                                              \
    } while (0)

    LOAD_STAGE(0, 0);
    LOAD_STAGE(1, 1);

    for (int s = 0; s < NKT; s++) {
        if (s + 2 < NKT) cp_wait<1>(); else cp_wait<0>();
        __syncthreads();
        if (s + 2 < NKT) LOAD_STAGE(s + 2, (s + 2) % NSTAGE);

        const uint32_t sb = sbase + (s % NSTAGE) * STAGE_BYTES;
        #pragma unroll
        for (int kk = 0; kk < 4; kk++) {
            uint32_t afr[2][4];
            uint32_t bfr[4][2];
            #pragma unroll
            for (int im = 0; im < 2; im++)
                ldsm4(afr[im][0], afr[im][1], afr[im][2], afr[im][3],
                      sb + a_row_off[im] + (((kk * 2 + a_hi) ^ swz) << 4));
            #pragma unroll
            for (int j2 = 0; j2 < 2; j2++) {
                uint32_t r0, r1, r2, r3;
                ldsm4(r0, r1, r2, r3,
                      sb + b_row_off[j2] + (((kk * 2 + b_hi) ^ swz) << 4));
                bfr[j2 * 2 + 0][0] = r0; bfr[j2 * 2 + 0][1] = r1;
                bfr[j2 * 2 + 1][0] = r2; bfr[j2 * 2 + 1][1] = r3;
            }
            #pragma unroll
            for (int im = 0; im < 2; im++)
                #pragma unroll
                for (int jn = 0; jn < 4; jn++)
                    mma16816(acc[im][jn], afr[im], bfr[jn]);
        }
    }

    // ---- epilogue: write Mw fp16 ----
    __half* mw = Mw_h + (size_t)k * TILEC;
    #pragma unroll
    for (int jn = 0; jn < 4; jn++) {
        const int n = n0 + wn + jn * 8 + (lane & 3) * 2;
        #pragma unroll
        for (int im = 0; im < 2; im++) {
            const int mrow = m0 + wm + im * 16 + (lane >> 2);
            const __half2 v0 = __float22half2_rn(make_float2(acc[im][jn][0], acc[im][jn][1]));
            const __half2 v1 = __float22half2_rn(make_float2(acc[im][jn][2], acc[im][jn][3]));
            *(__half2*)&mw[(size_t)mrow * NDIM + n]       = v0;
            *(__half2*)&mw[(size_t)(mrow + 8) * NDIM + n] = v1;
        }
    }
}

// ---------------------------------------------------------------------------
// Kernel 5: output transform Y = A^T M A + bias, scatter to out
// ---------------------------------------------------------------------------
__global__ __launch_bounds__(256) void output_transform_kernel(const float* __restrict__ bias,
                                                               float* __restrict__ out)
{
    const int tid  = threadIdx.x;
    const int tile = blockIdx.x * 2 + (tid >> 7);
    const int o    = (tid & 127) * 2;

    const int b  = tile >> 10;
    const int ty = (tile >> 5) & 31;
    const int tx = tile & 31;

    float2 M[4][4];
    #pragma unroll
    for (int a = 0; a < 4; a++)
        #pragma unroll
        for (int bb = 0; bb < 4; bb++)
            M[a][bb] = __half22float2(
                *(const __half2*)&Mw_h[(size_t)(a * 4 + bb) * TILEC + (size_t)tile * 256 + o]);

    float2 s0[4], s1[4];
    #pragma unroll
    for (int bb = 0; bb < 4; bb++) {
        s0[bb] = f2add(f2add(M[0][bb], M[1][bb]), M[2][bb]);
        s1[bb] = f2sub(f2sub(M[1][bb], M[2][bb]), M[3][bb]);
    }
    const float2 bv = *(const float2*)&bias[o];
    float2 Y00 = f2add(f2add(f2add(s0[0], s0[1]), s0[2]), bv);
    float2 Y01 = f2add(f2sub(f2sub(s0[1], s0[2]), s0[3]), bv);
    float2 Y10 = f2add(f2add(f2add(s1[0], s1[1]), s1[2]), bv);
    float2 Y11 = f2add(f2sub(f2sub(s1[1], s1[2]), s1[3]), bv);

    const int y0 = 2 * ty, x0 = 2 * tx;
    float* obase = out + ((size_t)b * H_ * W_) * NDIM + o;
    *(float2*)&obase[((size_t)y0 * W_ + x0) * NDIM]           = Y00;
    *(float2*)&obase[((size_t)y0 * W_ + x0 + 1) * NDIM]       = Y01;
    *(float2*)&obase[((size_t)(y0 + 1) * W_ + x0) * NDIM]     = Y10;
    *(float2*)&obase[((size_t)(y0 + 1) * W_ + x0 + 1) * NDIM] = Y11;
}

// ---------------------------------------------------------------------------
extern "C" void kernel_launch(void* const* d_in, const int* in_sizes, int n_in,
                              void* d_out, int out_size)
{
    const float* grid = (const float*)d_in[0];
    const float* Wd   = (const float*)d_in[1];
    const float* Wc   = (const float*)d_in[2];
    const float* bc   = (const float*)d_in[3];
    float* out        = (float*)d_out;

    cudaFuncSetAttribute(wino_gemm, cudaFuncAttributeMaxDynamicSharedMemorySize, SM_TOTAL);

    fold_weights_kernel<<<128, 256>>>(Wd, Wc);
    weight_transform_kernel<<<256, 256>>>();
    input_transform_kernel<<<NTILES / 2, 256>>>(grid);
    wino_gemm<<<dim3((NTILES / BM) * 2, 16), 256, SM_TOTAL>>>();
    output_transform_kernel<<<NTILES / 2, 256>>>(bc, out);
}

// round 8
// speedup vs baseline: 1.3874x; 1.0295x over previous
#include <cuda_runtime.h>
#include <cuda_fp16.h>
#include <cstdint>
#include <cstddef>

#define B_   16
#define H_   64
#define W_   64
#define C_   256
#define NDIM 256
#define NTILES 16384                 // 16 * 32 * 32 (2x2 output tiles)
#define TILEC  ((size_t)NTILES * 256)

// GEMM tiling (K = 256 per Winograd point; CTA loops a=0..3 for fixed b)
#define KD2  256
#define BM 64
#define BN 128
#define BK 64
#define NIT 16                       // 4 a-values x 4 BK-chunks
#define NSTAGE 3
#define A_BYTES (BM * 128)
#define B_BYTES (BN * 128)
#define STAGE_BYTES (A_BYTES + B_BYTES)   // 24 KB
#define SM_TOTAL (NSTAGE * STAGE_BYTES)   // 72 KB

__device__ __align__(16) float  Mf[(size_t)C_ * 256 * 8];          // [c][o][d] 2 MB
__device__ __align__(16) __half U_buf[(size_t)16 * 256 * 256];     // [k][o][c] 2 MB
__device__ __align__(16) __half V_buf[(size_t)16 * TILEC];         // [k][tile][c] 128 MB
__device__ __align__(16) __half Tw[(size_t)8 * TILEC];             // [b*2+p][tile][o] 64 MB

// ---------------------------------------------------------------------------
__device__ __forceinline__ uint32_t smem_u32(const void* p) {
    uint32_t a;
    asm("{ .reg .u64 t; cvta.to.shared.u64 t, %1; cvt.u32.u64 %0, t; }" : "=r"(a) : "l"(p));
    return a;
}
__device__ __forceinline__ void cp_async16(uint32_t dst, const void* src) {
    asm volatile("cp.async.cg.shared.global [%0], [%1], 16;" :: "r"(dst), "l"(src));
}
__device__ __forceinline__ void cp_commit() {
    asm volatile("cp.async.commit_group;" ::: "memory");
}
template<int N> __device__ __forceinline__ void cp_wait() {
    asm volatile("cp.async.wait_group %0;" :: "n"(N) : "memory");
}
__device__ __forceinline__ void ldsm4(uint32_t& r0, uint32_t& r1, uint32_t& r2, uint32_t& r3,
                                      uint32_t addr) {
    asm volatile("ldmatrix.sync.aligned.m8n8.x4.shared.b16 {%0,%1,%2,%3}, [%4];"
                 : "=r"(r0), "=r"(r1), "=r"(r2), "=r"(r3) : "r"(addr));
}
__device__ __forceinline__ void mma16816(float* d, const uint32_t* a, const uint32_t* b) {
    asm volatile(
        "mma.sync.aligned.m16n8k16.row.col.f32.f16.f16.f32 "
        "{%0,%1,%2,%3}, {%4,%5,%6,%7}, {%8,%9}, {%0,%1,%2,%3};\n"
        : "+f"(d[0]), "+f"(d[1]), "+f"(d[2]), "+f"(d[3])
        : "r"(a[0]), "r"(a[1]), "r"(a[2]), "r"(a[3]), "r"(b[0]), "r"(b[1]));
}
__device__ __forceinline__ float2 f2add(float2 a, float2 b) { return make_float2(a.x + b.x, a.y + b.y); }
__device__ __forceinline__ float2 f2sub(float2 a, float2 b) { return make_float2(a.x - b.x, a.y - b.y); }

// ---------------------------------------------------------------------------
// Kernel 1: fold weights -> Mf[c][o][d] (fp32)
// ---------------------------------------------------------------------------
__global__ void fold_weights_kernel(const float* __restrict__ Wd,
                                    const float* __restrict__ Wc)
{
    const int bid = blockIdx.x;
    const int d  = bid >> 4;
    const int ct = (bid >> 2) & 3;
    const int et = bid & 3;

    __shared__ float WdS[64][33];
    __shared__ float WcS[64][33];

    const int t  = threadIdx.x;
    const int tx = t & 15;
    const int ty = t >> 4;

    float acc[4][4];
    #pragma unroll
    for (int i = 0; i < 4; i++)
        #pragma unroll
        for (int j = 0; j < 4; j++) acc[i][j] = 0.0f;

    const float* WdBase = Wd + (size_t)d * C_ * C_ + (size_t)(ct * 64) * C_;
    const float* WcBase = Wc + (size_t)(et * 64) * (8 * C_) + d * C_;

    const int ci  = t >> 2;
    const int kk0 = (t & 3) * 8;

    for (int k0 = 0; k0 < C_; k0 += 32) {
        const float* srcA = WdBase + (size_t)ci * C_        + k0 + kk0;
        const float* srcB = WcBase + (size_t)ci * (8 * C_)  + k0 + kk0;
        #pragma unroll
        for (int u = 0; u < 8; u++) WdS[ci][kk0 + u] = srcA[u];
        #pragma unroll
        for (int u = 0; u < 8; u++) WcS[ci][kk0 + u] = srcB[u];
        __syncthreads();
        #pragma unroll
        for (int kk = 0; kk < 32; kk++) {
            float a[4], bb[4];
            #pragma unroll
            for (int i = 0; i < 4; i++) a[i]  = WdS[ty * 4 + i][kk];
            #pragma unroll
            for (int j = 0; j < 4; j++) bb[j] = WcS[tx * 4 + j][kk];
            #pragma unroll
            for (int i = 0; i < 4; i++)
                #pragma unroll
                for (int j = 0; j < 4; j++) acc[i][j] += a[i] * bb[j];
        }
        __syncthreads();
    }
    #pragma unroll
    for (int i = 0; i < 4; i++) {
        const int c = ct * 64 + ty * 4 + i;
        #pragma unroll
        for (int j = 0; j < 4; j++) {
            const int o = et * 64 + tx * 4 + j;
            Mf[((size_t)c * 256 + o) * 8 + d] = acc[i][j];
        }
    }
}

// ---------------------------------------------------------------------------
// Kernel 2: weight transform U_k = G K G^T  (k = a*4+b), fp16 [k][o][c]
// ---------------------------------------------------------------------------
__global__ __launch_bounds__(256) void weight_transform_kernel()
{
    const int o = blockIdx.x;
    const int c = threadIdx.x;

    const float* mp = &Mf[((size_t)c * 256 + o) * 8];
    float m[8];
    const float4 f0 = *(const float4*)(mp);
    const float4 f1 = *(const float4*)(mp + 4);
    m[0]=f0.x; m[1]=f0.y; m[2]=f0.z; m[3]=f0.w;
    m[4]=f1.x; m[5]=f1.y; m[6]=f1.z; m[7]=f1.w;

    float K[3][3];
    K[0][0]=m[3]; K[0][1]=m[4]; K[0][2]=m[5];
    K[1][0]=m[2]; K[1][1]=0.f;  K[1][2]=m[6];
    K[2][0]=m[1]; K[2][1]=m[0]; K[2][2]=m[7];

    float T[4][3];
    #pragma unroll
    for (int j = 0; j < 3; j++) {
        T[0][j] = K[0][j];
        T[1][j] = 0.5f * (K[0][j] + K[1][j] + K[2][j]);
        T[2][j] = 0.5f * (K[0][j] - K[1][j] + K[2][j]);
        T[3][j] = K[2][j];
    }
    #pragma unroll
    for (int a = 0; a < 4; a++) {
        float U0 = T[a][0];
        float U1 = 0.5f * (T[a][0] + T[a][1] + T[a][2]);
        float U2 = 0.5f * (T[a][0] - T[a][1] + T[a][2]);
        float U3 = T[a][2];
        U_buf[(size_t)(a * 4 + 0) * 65536 + o * 256 + c] = __float2half(U0);
        U_buf[(size_t)(a * 4 + 1) * 65536 + o * 256 + c] = __float2half(U1);
        U_buf[(size_t)(a * 4 + 2) * 65536 + o * 256 + c] = __float2half(U2);
        U_buf[(size_t)(a * 4 + 3) * 65536 + o * 256 + c] = __float2half(U3);
    }
}

// ---------------------------------------------------------------------------
// Kernel 3: FUSED pad + input transform (fp32 grid -> fp16 V)
// ---------------------------------------------------------------------------
__global__ __launch_bounds__(256) void input_transform_kernel(const float* __restrict__ g)
{
    const int tid  = threadIdx.x;
    const int tile = blockIdx.x * 2 + (tid >> 7);
    const int c    = (tid & 127) * 2;

    const int b  = tile >> 10;
    const int ty = (tile >> 5) & 31;
    const int tx = tile & 31;

    const int gy0 = 2 * ty - 1;
    const int gx0 = 2 * tx - 1;
    const float* gbase = g + ((size_t)b * H_ * W_) * C_ + c;

    float2 d[4][4];
    #pragma unroll
    for (int i = 0; i < 4; i++) {
        const int gy = gy0 + i;
        const bool vy = (gy >= 0) && (gy < H_);
        #pragma unroll
        for (int j = 0; j < 4; j++) {
            const int gx = gx0 + j;
            if (vy && gx >= 0 && gx < W_)
                d[i][j] = *(const float2*)(gbase + ((size_t)gy * W_ + gx) * C_);
            else
                d[i][j] = make_float2(0.0f, 0.0f);
        }
    }

    float2 tr[4][4];
    #pragma unroll
    for (int j = 0; j < 4; j++) {
        tr[0][j] = f2sub(d[0][j], d[2][j]);
        tr[1][j] = f2add(d[1][j], d[2][j]);
        tr[2][j] = f2sub(d[2][j], d[1][j]);
        tr[3][j] = f2sub(d[1][j], d[3][j]);
    }
    #pragma unroll
    for (int a = 0; a < 4; a++) {
        float2 V0 = f2sub(tr[a][0], tr[a][2]);
        float2 V1 = f2add(tr[a][1], tr[a][2]);
        float2 V2 = f2sub(tr[a][2], tr[a][1]);
        float2 V3 = f2sub(tr[a][1], tr[a][3]);
        *(__half2*)&V_buf[(size_t)(a * 4 + 0) * TILEC + (size_t)tile * 256 + c] = __float22half2_rn(V0);
        *(__half2*)&V_buf[(size_t)(a * 4 + 1) * TILEC + (size_t)tile * 256 + c] = __float22half2_rn(V1);
        *(__half2*)&V_buf[(size_t)(a * 4 + 2) * TILEC + (size_t)tile * 256 + c] = __float22half2_rn(V2);
        *(__half2*)&V_buf[(size_t)(a * 4 + 3) * TILEC + (size_t)tile * 256 + c] = __float22half2_rn(V3);
    }
}

// ---------------------------------------------------------------------------
// Kernel 4: GEMM with fused Winograd row-combine.
// CTA = (m-block, n-half, b). Loops a=0..3: M_a = V_{a*4+b} @ U_{a*4+b}^T,
// folds into T_p = sum_a A_p[a] * M_a (fp16x2 accumulators), writes Tw.
// ---------------------------------------------------------------------------
__global__ __launch_bounds__(256, 2) void wino_gemm_T(void)
{
    extern __shared__ __align__(1024) char smem[];
    const uint32_t sbase = smem_u32(smem);

    const int t    = threadIdx.x;
    const int warp = t >> 5, lane = t & 31;
    const int bx   = blockIdx.x;
    const int n0   = (bx & 1) * BN;
    const int bfix = (bx >> 1) & 3;
    const int m0   = (bx >> 3) * BM;

    // ---- producer setup ----
    const int arow   = t >> 2;
    const int acpair = (t & 3) * 2;
    const int brow = t >> 1;
    const int bc0  = (t & 1) * 4;

    // base pointers at k = bfix (a=0); per-iteration offset added below
    const __half* a_base = V_buf + (size_t)bfix * TILEC + (size_t)(m0 + arow) * KD2 + acpair * 8;
    const __half* b_base = U_buf + (size_t)bfix * 65536 + (size_t)(n0 + brow) * KD2 + bc0 * 8;

    uint32_t a_dst[2], b_dst[4];
    #pragma unroll
    for (int j = 0; j < 2; j++)
        a_dst[j] = (uint32_t)(arow * 128 + (((acpair + j) ^ (arow & 7)) << 4));
    #pragma unroll
    for (int j = 0; j < 4; j++)
        b_dst[j] = (uint32_t)(A_BYTES + brow * 128 + (((bc0 + j) ^ (brow & 7)) << 4));

    // ---- consumer setup: warp tile 32x32 ----
    const int wm = (warp >> 2) * 32;
    const int wn = (warp & 3) * 32;
    const int swz  = lane & 7;
    const int a_hi = lane >> 4;
    const int b_hi = (lane >> 3) & 1;

    uint32_t a_row_off[2], b_row_off[2];
    #pragma unroll
    for (int im = 0; im < 2; im++)
        a_row_off[im] = (uint32_t)((wm + im * 16 + (lane & 15)) * 128);
    #pragma unroll
    for (int j2 = 0; j2 < 2; j2++)
        b_row_off[j2] = (uint32_t)(A_BYTES +
            (wn + j2 * 16 + ((lane >> 4) << 3) + (lane & 7)) * 128);

    float acc[2][4][4];
    #pragma unroll
    for (int i = 0; i < 2; i++)
        #pragma unroll
        for (int j = 0; j < 4; j++)
            #pragma unroll
            for (int r = 0; r < 4; r++) acc[i][j][r] = 0.0f;

    // T accumulators: [p][im][jn][pair] as half2
    __half2 Tacc[2][2][4][2];
    #pragma unroll
    for (int p = 0; p < 2; p++)
        #pragma unroll
        for (int i = 0; i < 2; i++)
            #pragma unroll
            for (int j = 0; j < 4; j++) {
                Tacc[p][i][j][0] = __half2half2(__float2half(0.0f));
                Tacc[p][i][j][1] = __half2half2(__float2half(0.0f));
            }

    // iteration i: a = i>>2, kt = i&3; source offset = (i&~3)*TILEC-ish
    #define LOAD_STAGE(I, S)                                                       \
    do {                                                                           \
        const int a_  = (I) >> 2;                                                  \
        const int kt_ = (I) & 3;                                                   \
        const __half* asrc = a_base + (size_t)(a_ * 4) * TILEC + kt_ * 64;         \
        const __half* bsrc = b_base + (size_t)(a_ * 4) * 65536 + kt_ * 64;         \
        const uint32_t sb  = sbase + (S) * STAGE_BYTES;                            \
        _Pragma("unroll")                                                          \
        for (int j = 0; j < 2; j++) cp_async16(sb + a_dst[j], asrc + j * 8);       \
        _Pragma("unroll")                                                          \
        for (int j = 0; j < 4; j++) cp_async16(sb + b_dst[j], bsrc + j * 8);       \
        cp_commit();                                                               \
    } while (0)

    LOAD_STAGE(0, 0);
    LOAD_STAGE(1, 1);

    for (int s = 0; s < NIT; s++) {
        if (s + 2 < NIT) cp_wait<1>(); else cp_wait<0>();
        __syncthreads();
        if (s + 2 < NIT) LOAD_STAGE(s + 2, (s + 2) % NSTAGE);

        const uint32_t sb = sbase + (s % NSTAGE) * STAGE_BYTES;
        #pragma unroll
        for (int kk = 0; kk < 4; kk++) {
            uint32_t afr[2][4];
            uint32_t bfr[4][2];
            #pragma unroll
            for (int im = 0; im < 2; im++)
                ldsm4(afr[im][0], afr[im][1], afr[im][2], afr[im][3],
                      sb + a_row_off[im] + (((kk * 2 + a_hi) ^ swz) << 4));
            #pragma unroll
            for (int j2 = 0; j2 < 2; j2++) {
                uint32_t r0, r1, r2, r3;
                ldsm4(r0, r1, r2, r3,
                      sb + b_row_off[j2] + (((kk * 2 + b_hi) ^ swz) << 4));
                bfr[j2 * 2 + 0][0] = r0; bfr[j2 * 2 + 0][1] = r1;
                bfr[j2 * 2 + 1][0] = r2; bfr[j2 * 2 + 1][1] = r3;
            }
            #pragma unroll
            for (int im = 0; im < 2; im++)
                #pragma unroll
                for (int jn = 0; jn < 4; jn++)
                    mma16816(acc[im][jn], afr[im], bfr[jn]);
        }

        // end of an a-group: fold M into T, zero M
        if ((s & 3) == 3) {
            const int a = s >> 2;
            // A0 = [1,1,1,0], A1 = [0,1,-1,-1]
            const float c0 = (a < 3) ? 1.0f : 0.0f;
            const float c1 = (a == 0) ? 0.0f : ((a == 1) ? 1.0f : -1.0f);
            const __half2 h0 = __float2half2_rn(c0);
            const __half2 h1 = __float2half2_rn(c1);
            #pragma unroll
            for (int im = 0; im < 2; im++)
                #pragma unroll
                for (int jn = 0; jn < 4; jn++) {
                    const __half2 mlo = __float22half2_rn(make_float2(acc[im][jn][0], acc[im][jn][1]));
                    const __half2 mhi = __float22half2_rn(make_float2(acc[im][jn][2], acc[im][jn][3]));
                    Tacc[0][im][jn][0] = __hfma2(h0, mlo, Tacc[0][im][jn][0]);
                    Tacc[0][im][jn][1] = __hfma2(h0, mhi, Tacc[0][im][jn][1]);
                    Tacc[1][im][jn][0] = __hfma2(h1, mlo, Tacc[1][im][jn][0]);
                    Tacc[1][im][jn][1] = __hfma2(h1, mhi, Tacc[1][im][jn][1]);
                    acc[im][jn][0] = 0.0f; acc[im][jn][1] = 0.0f;
                    acc[im][jn][2] = 0.0f; acc[im][jn][3] = 0.0f;
                }
        }
    }

    // ---- epilogue: write T0, T1 (fp16) to Tw[(b*2+p)][tile][o] ----
    const int g = lane >> 2;
    #pragma unroll
    for (int p = 0; p < 2; p++) {
        __half* tw = Tw + (size_t)(bfix * 2 + p) * TILEC;
        #pragma unroll
        for (int jn = 0; jn < 4; jn++) {
            const int n = n0 + wn + jn * 8 + (lane & 3) * 2;
            #pragma unroll
            for (int im = 0; im < 2; im++) {
                const int mrow = m0 + wm + im * 16 + g;
                *(__half2*)&tw[(size_t)mrow * NDIM + n]       = Tacc[p][im][jn][0];
                *(__half2*)&tw[(size_t)(mrow + 8) * NDIM + n] = Tacc[p][im][jn][1];
            }
        }
    }
}

// ---------------------------------------------------------------------------
// Kernel 5: output column-combine Y_pq = sum_b A_q[b] T_pb + bias, scatter.
// ---------------------------------------------------------------------------
__global__ __launch_bounds__(256) void output_transform_kernel(const float* __restrict__ bias,
                                                               float* __restrict__ out)
{
    const int tid  = threadIdx.x;
    const int tile = blockIdx.x * 2 + (tid >> 7);
    const int o    = (tid & 127) * 2;

    const int b  = tile >> 10;
    const int ty = (tile >> 5) & 31;
    const int tx = tile & 31;

    float2 tv[4][2];
    #pragma unroll
    for (int bb = 0; bb < 4; bb++)
        #pragma unroll
        for (int p = 0; p < 2; p++)
            tv[bb][p] = __half22float2(
                *(const __half2*)&Tw[(size_t)(bb * 2 + p) * TILEC + (size_t)tile * 256 + o]);

    const float2 bv = *(const float2*)&bias[o];
    float2 Y00 = f2add(f2add(f2add(tv[0][0], tv[1][0]), tv[2][0]), bv);
    float2 Y01 = f2add(f2sub(f2sub(tv[1][0], tv[2][0]), tv[3][0]), bv);
    float2 Y10 = f2add(f2add(f2add(tv[0][1], tv[1][1]), tv[2][1]), bv);
    float2 Y11 = f2add(f2sub(f2sub(tv[1][1], tv[2][1]), tv[3][1]), bv);

    const int y0 = 2 * ty, x0 = 2 * tx;
    float* obase = out + ((size_t)b * H_ * W_) * NDIM + o;
    *(float2*)&obase[((size_t)y0 * W_ + x0) * NDIM]           = Y00;
    *(float2*)&obase[((size_t)y0 * W_ + x0 + 1) * NDIM]       = Y01;
    *(float2*)&obase[((size_t)(y0 + 1) * W_ + x0) * NDIM]     = Y10;
    *(float2*)&obase[((size_t)(y0 + 1) * W_ + x0 + 1) * NDIM] = Y11;
}

// ---------------------------------------------------------------------------
extern "C" void kernel_launch(void* const* d_in, const int* in_sizes, int n_in,
                              void* d_out, int out_size)
{
    const float* grid = (const float*)d_in[0];
    const float* Wd   = (const float*)d_in[1];
    const float* Wc   = (const float*)d_in[2];
    const float* bc   = (const float*)d_in[3];
    float* out        = (float*)d_out;

    cudaFuncSetAttribute(wino_gemm_T, cudaFuncAttributeMaxDynamicSharedMemorySize, SM_TOTAL);

    fold_weights_kernel<<<128, 256>>>(Wd, Wc);
    weight_transform_kernel<<<256, 256>>>();
    input_transform_kernel<<<NTILES / 2, 256>>>(grid);
    wino_gemm_T<<<(NTILES / BM) * 2 * 4, 256, SM_TOTAL>>>();
    output_transform_kernel<<<NTILES / 2, 256>>>(bc, out);
}